// round 13
// baseline (speedup 1.0000x reference)
#include <cuda_runtime.h>
#include <cuda_fp16.h>
#include <math.h>

#define N_NODES 100000
#define IN_C 128
#define HID_C 128
#define OUT_C 64
#define N_EDGES 1600000

#define SCAN_BLK 512
#define NB1 ((N_NODES + SCAN_BLK - 1) / SCAN_BLK)   // 196

#define NCHUNK 4
#define CHUNK_N ((N_NODES + NCHUNK - 1) / NCHUNK)   // 25000

// ---------------- scratch (device globals: no allocations allowed) ----------
__device__ __align__(16) float  g_dinv[N_NODES];
__device__ __align__(16) __half g_h1[(size_t)N_NODES * HID_C];  // x @ W1 (fp16)
__device__ __align__(16) __half g_a1[(size_t)N_NODES * HID_C];  // layer-1 out (fp16)
__device__ __align__(16) __half g_h2[(size_t)N_NODES * OUT_C];  // relu(a1) @ W2 (fp16)
__device__ __align__(16) int2   g_csre[N_EDGES];     // packed {row, bits(dinv[row])}
__device__ __align__(16) int    g_cnt[N_NODES];      // per-col degree (no self-loop)
__device__ __align__(16) int    g_incl[N_NODES];     // inclusive scan within block
__device__ __align__(16) int    g_part[256];         // block partial sums
__device__ __align__(16) int    g_partoff[256];      // exclusive block offsets
__device__ __align__(16) int    g_ptr[N_NODES + 1];  // CSR pointers (by col)
__device__ __align__(16) int    g_cur[N_NODES];      // fill cursors
__device__ int g_is64;

// ---------------- f32x2 packed-FMA helpers ------------------------------------
__device__ __forceinline__ unsigned long long pack_dup(float x) {
    unsigned long long r;
    asm("mov.b64 %0, {%1, %1};" : "=l"(r) : "f"(x));
    return r;
}
__device__ __forceinline__ void fma2(unsigned long long& d,
                                     unsigned long long a, unsigned long long b) {
    asm("fma.rn.f32x2 %0, %1, %2, %0;" : "+l"(d) : "l"(a), "l"(b));
}
__device__ __forceinline__ void unpack2(unsigned long long v, float& lo, float& hi) {
    asm("mov.b64 {%0, %1}, %2;" : "=f"(lo), "=f"(hi) : "l"(v));
}

// ---------------- edge decode (shared by hist + fill) --------------------------
__device__ __forceinline__ void decode_edge(const void* __restrict__ ei, int e,
                                            int& r, int& c) {
    if (g_is64) {
        const long long* p = (const long long*)ei;
        r = (int)p[e];
        c = (int)p[N_EDGES + e];
    } else {
        const int* p = (const int*)ei;
        r = p[e];
        c = p[N_EDGES + e];
    }
    r = min(max(r, 0), N_NODES - 1);
    c = min(max(c, 0), N_NODES - 1);
}

// int64 layout: odd 32-bit words all zero (indices < 2^17). 32 threads, ballot.
__global__ void detect_kernel(const unsigned int* __restrict__ ei32) {
    int t = threadIdx.x;
    unsigned nz = (ei32[2 * t + 1] != 0u) ? 1u : 0u;
    unsigned m = __ballot_sync(0xffffffffu, nz);
    if (t == 0) g_is64 = (m == 0u) ? 1 : 0;
}

__global__ void zero_cnt_kernel() {
    int i = blockIdx.x * blockDim.x + threadIdx.x;
    if (i < N_NODES) g_cnt[i] = 0;
}

__global__ void hist_kernel(const void* __restrict__ ei) {
    int e = blockIdx.x * blockDim.x + threadIdx.x;
    if (e >= N_EDGES) return;
    int r, c;
    decode_edge(ei, e, r, c);
    atomicAdd(&g_cnt[c], 1);
}

// ---------------- prefix scan + CSR fill --------------------------------------
__global__ __launch_bounds__(SCAN_BLK) void scan1_kernel() {
    __shared__ int s[SCAN_BLK];
    int t = threadIdx.x;
    int i = blockIdx.x * SCAN_BLK + t;
    int v = (i < N_NODES) ? g_cnt[i] : 0;
    s[t] = v;
    __syncthreads();
    for (int off = 1; off < SCAN_BLK; off <<= 1) {
        int add = (t >= off) ? s[t - off] : 0;
        __syncthreads();
        s[t] += add;
        __syncthreads();
    }
    if (i < N_NODES) g_incl[i] = s[t];
    if (t == SCAN_BLK - 1) g_part[blockIdx.x] = s[t];
}

__global__ __launch_bounds__(256) void scan2_kernel() {
    __shared__ int s[256];
    int t = threadIdx.x;
    int v = (t < NB1) ? g_part[t] : 0;
    s[t] = v;
    __syncthreads();
    for (int off = 1; off < 256; off <<= 1) {
        int add = (t >= off) ? s[t - off] : 0;
        __syncthreads();
        s[t] += add;
        __syncthreads();
    }
    g_partoff[t] = s[t] - v;   // exclusive
}

__global__ void scan3_kernel() {
    int i = blockIdx.x * blockDim.x + threadIdx.x;
    if (i >= N_NODES) return;
    int cnt  = g_cnt[i];
    int excl = g_partoff[i / SCAN_BLK] + g_incl[i] - cnt;
    g_ptr[i] = excl;
    g_cur[i] = excl;
    g_dinv[i] = rsqrtf((float)cnt + 1.0f);
    if (i == 0) g_ptr[N_NODES] = N_EDGES;
}

__global__ void csr_fill_kernel(const void* __restrict__ ei) {
    int e = blockIdx.x * blockDim.x + threadIdx.x;
    if (e >= N_EDGES) return;
    int r, c;
    decode_edge(ei, e, r, c);
    int pos = atomicAdd(&g_cur[c], 1);
    g_csre[pos] = make_int2(r, __float_as_int(g_dinv[r]));
}

// ---------------- GEMM: H = (relu?)X @ W, f32x2 FMA, fp16 output --------------
// n_base: starting node of this launch's range (chunked pipelining for LAYER 2).
template <int LAYER>
__global__ __launch_bounds__(256) void gemm_kernel(
    const float* __restrict__ X,       // used only for LAYER==1
    const float* __restrict__ W,
    int n_base, int n_limit)
{
    constexpr int FIN   = 128;
    constexpr int FOUT  = (LAYER == 1) ? HID_C : OUT_C;
    constexpr int NTILE = 64;
    constexpr int KSTEP = 32;
    constexpr int CH    = (FOUT * NTILE) / (256 * 4);  // 8 / 4
    constexpr int PAIRS = CH / 2;                      // 4 / 2
    constexpr int PITCH = NTILE + 1;

    __shared__ float sW[KSTEP * FOUT];
    __shared__ float sXT[KSTEP * PITCH];

    const int tid = threadIdx.x;
    const int n0  = n_base + blockIdx.x * NTILE;

    const int cg = tid % (FOUT / CH);
    const int ng = tid / (FOUT / CH);
    const int j0 = cg * CH;
    const int m0 = ng * 4;

    unsigned long long acc2[4][PAIRS];
    #pragma unroll
    for (int a = 0; a < 4; a++)
        #pragma unroll
        for (int b = 0; b < PAIRS; b++) acc2[a][b] = 0ULL;

    for (int k0 = 0; k0 < FIN; k0 += KSTEP) {
        __syncthreads();
        {
            const float4* W4  = (const float4*)(W + (size_t)k0 * FOUT);
            float4*       sW4 = (float4*)sW;
            constexpr int CNT = KSTEP * FOUT / 4;
            #pragma unroll
            for (int i = tid; i < CNT; i += 256) sW4[i] = W4[i];
        }
        {
            constexpr int CNT = KSTEP * NTILE;
            #pragma unroll
            for (int i = tid; i < CNT; i += 256) {
                int k = i % KSTEP;
                int m = i / KSTEP;
                int n = n0 + m;
                float v = 0.0f;
                if (n < n_limit) {
                    if (LAYER == 1) {
                        v = X[(size_t)n * FIN + k0 + k];
                    } else {
                        v = fmaxf(__half2float(g_a1[(size_t)n * FIN + k0 + k]), 0.0f);
                    }
                }
                sXT[k * PITCH + m] = v;
            }
        }
        __syncthreads();

        #pragma unroll 8
        for (int k = 0; k < KSTEP; k++) {
            unsigned long long w2[PAIRS];
            #pragma unroll
            for (int p = 0; p < PAIRS; p++)
                w2[p] = *(const unsigned long long*)&sW[k * FOUT + j0 + 2 * p];
            unsigned long long xp[4];
            #pragma unroll
            for (int mi = 0; mi < 4; mi++)
                xp[mi] = pack_dup(sXT[k * PITCH + m0 + mi]);
            #pragma unroll
            for (int mi = 0; mi < 4; mi++)
                #pragma unroll
                for (int p = 0; p < PAIRS; p++)
                    fma2(acc2[mi][p], xp[mi], w2[p]);
        }
    }

    __half* Hout = (LAYER == 1) ? g_h1 : g_h2;
    #pragma unroll
    for (int mi = 0; mi < 4; mi++) {
        int n = n0 + m0 + mi;
        if (n < n_limit) {
            #pragma unroll
            for (int p = 0; p < PAIRS; p++) {
                float lo, hi;
                unpack2(acc2[mi][p], lo, hi);
                __half2 h2v = __floats2half2_rn(lo, hi);
                *(__half2*)&Hout[(size_t)n * FOUT + j0 + 2 * p] = h2v;
            }
        }
    }
}

// ---------------- CSR gather: one WARP per destination node -------------------
// agg[c] = dinv[c] * sum_j dinv[r_j] * H[r_j]  +  dinv[c]^2 * H[c]  +  bias
// n_base: starting node of this launch's chunk.
template <int FOUT, bool OUT_HALF>
__global__ __launch_bounds__(256) void gather_kernel(
    const __half* __restrict__ H,
    const float* __restrict__ bias,
    void* __restrict__ Aout,
    int n_base, int n_limit)
{
    constexpr int VEC = FOUT / 32;   // halves per lane: 4 or 2
    const int node = n_base + ((blockIdx.x * 256 + threadIdx.x) >> 5);
    const int lane = threadIdx.x & 31;
    if (node >= n_limit) return;

    const int beg = g_ptr[node];
    const int end = g_ptr[node + 1];
    const float dc = g_dinv[node];

    float acc[VEC];
    #pragma unroll
    for (int v = 0; v < VEC; v++) acc[v] = 0.0f;

    for (int base = beg; base < end; base += 32) {
        int j = base + lane;
        int2 meta = (j < end) ? g_csre[j] : make_int2(0, 0);
        int cnt = min(32, end - base);
        #pragma unroll 8
        for (int i = 0; i < cnt; i++) {
            int   r = __shfl_sync(0xffffffffu, meta.x, i);
            float w = __int_as_float(__shfl_sync(0xffffffffu, meta.y, i));
            const __half* row = H + (size_t)r * FOUT + lane * VEC;
            if (VEC == 4) {
                uint2 u = *(const uint2*)row;
                float2 f0 = __half22float2(*(const __half2*)&u.x);
                float2 f1 = __half22float2(*(const __half2*)&u.y);
                acc[0] = fmaf(w, f0.x, acc[0]);
                acc[1] = fmaf(w, f0.y, acc[1]);
                acc[2] = fmaf(w, f1.x, acc[2]);
                acc[3] = fmaf(w, f1.y, acc[3]);
            } else {
                unsigned u = *(const unsigned*)row;
                float2 f0 = __half22float2(*(const __half2*)&u);
                acc[0] = fmaf(w, f0.x, acc[0]);
                acc[1] = fmaf(w, f0.y, acc[1]);
            }
        }
    }

    const float d2 = dc * dc;
    const __half* srow = H + (size_t)node * FOUT + lane * VEC;
    float o[VEC];
    if (VEC == 4) {
        uint2 u = *(const uint2*)srow;
        float2 s0 = __half22float2(*(const __half2*)&u.x);
        float2 s1 = __half22float2(*(const __half2*)&u.y);
        const float4 b = *(const float4*)(bias + lane * 4);
        o[0] = fmaf(dc, acc[0], fmaf(d2, s0.x, b.x));
        o[1] = fmaf(dc, acc[1], fmaf(d2, s0.y, b.y));
        o[2] = fmaf(dc, acc[2], fmaf(d2, s1.x, b.z));
        o[3] = fmaf(dc, acc[3], fmaf(d2, s1.y, b.w));
    } else {
        unsigned u = *(const unsigned*)srow;
        float2 s0 = __half22float2(*(const __half2*)&u);
        const float2 b = *(const float2*)(bias + lane * 2);
        o[0] = fmaf(dc, acc[0], fmaf(d2, s0.x, b.x));
        o[1] = fmaf(dc, acc[1], fmaf(d2, s0.y, b.y));
    }

    if (OUT_HALF) {
        __half* orow = (__half*)Aout + (size_t)node * FOUT + lane * VEC;
        if (VEC == 4) {
            uint2 u;
            *(__half2*)&u.x = __floats2half2_rn(o[0], o[1]);
            *(__half2*)&u.y = __floats2half2_rn(o[2], o[3]);
            *(uint2*)orow = u;
        } else {
            *(__half2*)orow = __floats2half2_rn(o[0], o[1]);
        }
    } else {
        float* orow = (float*)Aout + (size_t)node * FOUT + lane * VEC;
        if (VEC == 4) {
            *(float4*)orow = make_float4(o[0], o[1], o[2], o[3]);
        } else {
            *(float2*)orow = make_float2(o[0], o[1]);
        }
    }
}

// ---------------- launch ------------------------------------------------------
extern "C" void kernel_launch(void* const* d_in, const int* in_sizes, int n_in,
                              void* d_out, int out_size)
{
    // identify inputs by element count (ordering-proof; all counts distinct)
    const float* x  = nullptr; const void* ei = nullptr;
    const float* W1 = nullptr; const float* b1 = nullptr;
    const float* W2 = nullptr; const float* b2 = nullptr;
    for (int i = 0; i < n_in; i++) {
        switch (in_sizes[i]) {
            case N_NODES * IN_C:   x  = (const float*)d_in[i]; break;
            case 2 * N_EDGES:      ei = d_in[i];               break;
            case IN_C * HID_C:     W1 = (const float*)d_in[i]; break;
            case HID_C:            b1 = (const float*)d_in[i]; break;
            case HID_C * OUT_C:    W2 = (const float*)d_in[i]; break;
            case OUT_C:            b2 = (const float*)d_in[i]; break;
            default: break;
        }
    }
    float* out = (float*)d_out;

    __half* p_h1; cudaGetSymbolAddress((void**)&p_h1, g_h1);
    __half* p_a1; cudaGetSymbolAddress((void**)&p_a1, g_a1);
    __half* p_h2; cudaGetSymbolAddress((void**)&p_h2, g_h2);

    // side stream + events, created once (first call is uncaptured)
    static cudaStream_t s2 = nullptr;
    static cudaEvent_t ev_fork = nullptr, ev_join = nullptr;
    static cudaEvent_t ev_chunk[NCHUNK], ev_l2done = nullptr;
    if (s2 == nullptr) {
        cudaStreamCreateWithFlags(&s2, cudaStreamNonBlocking);
        cudaEventCreateWithFlags(&ev_fork, cudaEventDisableTiming);
        cudaEventCreateWithFlags(&ev_join, cudaEventDisableTiming);
        cudaEventCreateWithFlags(&ev_l2done, cudaEventDisableTiming);
        for (int k = 0; k < NCHUNK; k++)
            cudaEventCreateWithFlags(&ev_chunk[k], cudaEventDisableTiming);
    }

    // ---- fork: CSR build on s2, GEMM1 on default stream (independent) ----
    cudaEventRecord(ev_fork, 0);
    cudaStreamWaitEvent(s2, ev_fork, 0);

    detect_kernel<<<1, 32, 0, s2>>>((const unsigned int*)ei);
    zero_cnt_kernel<<<(N_NODES + 255) / 256, 256, 0, s2>>>();
    hist_kernel<<<(N_EDGES + 255) / 256, 256, 0, s2>>>(ei);
    scan1_kernel<<<NB1, SCAN_BLK, 0, s2>>>();
    scan2_kernel<<<1, 256, 0, s2>>>();
    scan3_kernel<<<(N_NODES + 255) / 256, 256, 0, s2>>>();
    csr_fill_kernel<<<(N_EDGES + 255) / 256, 256, 0, s2>>>(ei);
    cudaEventRecord(ev_join, s2);

    gemm_kernel<1><<<(N_NODES + 63) / 64, 256>>>(x, W1, 0, N_NODES);

    // ---- join: gather1 needs both h1 (default) and CSR+dinv (s2) ----
    cudaStreamWaitEvent(0, ev_join, 0);

    // ---- pipelined: gather1(chunk k) on s0, GEMM2(chunk k) on s2 ----
    for (int k = 0; k < NCHUNK; k++) {
        int base  = k * CHUNK_N;
        int limit = min(N_NODES, base + CHUNK_N);
        int nn    = limit - base;
        gather_kernel<HID_C, true><<<(nn * 32 + 255) / 256, 256>>>(p_h1, b1, p_a1, base, limit);
        cudaEventRecord(ev_chunk[k], 0);
        cudaStreamWaitEvent(s2, ev_chunk[k], 0);
        gemm_kernel<2><<<(nn + 63) / 64, 256, 0, s2>>>(nullptr, W2, base, limit);
    }
    cudaEventRecord(ev_l2done, s2);
    cudaStreamWaitEvent(0, ev_l2done, 0);

    // gather2 needs all h2 (neighbors are random): full-range, direct to d_out
    gather_kernel<OUT_C, false><<<(N_NODES * 32 + 255) / 256, 256>>>(p_h2, b2, out, 0, N_NODES);
}